// round 1
// baseline (speedup 1.0000x reference)
#include <cuda_runtime.h>
#include <math.h>

// Problem constants
#define B_    2
#define S_    2048
#define DIM_  2048
#define H_    16
#define DH_   128
#define MROWS (B_ * S_)   // 4096

// Scratch in device globals (allocation-free rule)
__device__ float g_q [MROWS * DIM_];
__device__ float g_k [MROWS * DIM_];
__device__ float g_v [MROWS * DIM_];
__device__ float g_ot[MROWS * DIM_];

// ---------------------------------------------------------------------------
// SGEMM: C[M,N] = A[M,K] @ B[N,K]^T   (both row-major, reduce over K)
// 128x128 block tile, BK=8, 256 threads, 8x8 register tile per thread.
// ---------------------------------------------------------------------------
__global__ __launch_bounds__(256) void sgemm_abt(const float* __restrict__ A,
                                                 const float* __restrict__ Bm,
                                                 float* __restrict__ C,
                                                 int M, int N, int K)
{
    __shared__ float As[8][128];
    __shared__ float Bs[8][128];

    const int bm  = blockIdx.y * 128;
    const int bn  = blockIdx.x * 128;
    const int tid = threadIdx.x;
    const int tr  = tid >> 4;          // 0..15
    const int tc  = tid & 15;          // 0..15
    const int lrow = tid >> 1;         // 0..127
    const int lk   = (tid & 1) << 2;   // 0 or 4

    const float* Aptr = A  + (size_t)(bm + lrow) * K + lk;
    const float* Bptr = Bm + (size_t)(bn + lrow) * K + lk;

    float acc[8][8];
#pragma unroll
    for (int i = 0; i < 8; i++)
#pragma unroll
        for (int j = 0; j < 8; j++) acc[i][j] = 0.f;

    for (int k0 = 0; k0 < K; k0 += 8) {
        float4 a = *(const float4*)(Aptr + k0);
        float4 b = *(const float4*)(Bptr + k0);
        __syncthreads();
        As[lk + 0][lrow] = a.x; As[lk + 1][lrow] = a.y;
        As[lk + 2][lrow] = a.z; As[lk + 3][lrow] = a.w;
        Bs[lk + 0][lrow] = b.x; Bs[lk + 1][lrow] = b.y;
        Bs[lk + 2][lrow] = b.z; Bs[lk + 3][lrow] = b.w;
        __syncthreads();
#pragma unroll
        for (int kk = 0; kk < 8; kk++) {
            float ar[8], br[8];
            *(float4*)&ar[0] = *(const float4*)&As[kk][tr * 8];
            *(float4*)&ar[4] = *(const float4*)&As[kk][tr * 8 + 4];
            *(float4*)&br[0] = *(const float4*)&Bs[kk][tc * 8];
            *(float4*)&br[4] = *(const float4*)&Bs[kk][tc * 8 + 4];
#pragma unroll
            for (int i = 0; i < 8; i++)
#pragma unroll
                for (int j = 0; j < 8; j++)
                    acc[i][j] = fmaf(ar[i], br[j], acc[i][j]);
        }
    }

#pragma unroll
    for (int i = 0; i < 8; i++) {
        float* cp = C + (size_t)(bm + tr * 8 + i) * N + bn + tc * 8;
        float4 o0 = make_float4(acc[i][0], acc[i][1], acc[i][2], acc[i][3]);
        float4 o1 = make_float4(acc[i][4], acc[i][5], acc[i][6], acc[i][7]);
        *(float4*)cp       = o0;
        *(float4*)(cp + 4) = o1;
    }
}

// ---------------------------------------------------------------------------
// RoPE: in-place on Q and K. Pair (2i, 2i+1) within each head.
// grid covers MROWS * (DIM_/2) pairs.
// ---------------------------------------------------------------------------
__global__ void rope_kernel(float* __restrict__ q, float* __restrict__ k,
                            const float* __restrict__ cosb,
                            const float* __restrict__ sinb)
{
    int idx = blockIdx.x * blockDim.x + threadIdx.x;   // 0 .. MROWS*1024-1
    int row = idx >> 10;           // 0..4095
    int pp  = idx & 1023;          // pair index within row
    int i   = pp & 63;             // freq index within head (DH/2 = 64)
    int hh  = pp >> 6;             // head
    int col = (hh << 7) + (i << 1);
    int s   = row & (S_ - 1);

    float c  = cosb[s * 64 + i];
    float sn = sinb[s * 64 + i];

    size_t off = (size_t)row * DIM_ + col;
    float2 qv = *(float2*)(q + off);
    float2 kv = *(float2*)(k + off);
    *(float2*)(q + off) = make_float2(qv.x * c - qv.y * sn, qv.x * sn + qv.y * c);
    *(float2*)(k + off) = make_float2(kv.x * c - kv.y * sn, kv.x * sn + kv.y * c);
}

// ---------------------------------------------------------------------------
// Flash attention, fp32, causal. TQ=TK=64, DH=128, 256 threads.
// Writes O transposed: Ot[b, h*128 + dh, s]  (matches reference reshape quirk)
// Shared layout (floats):
//   Qt[128][64]   (transposed Q tile)
//   Kt[128][64]   (transposed K tile)
//   Vs[64][132]   (natural, padded)
//   Ps[64][65]    (probabilities, padded)
// ---------------------------------------------------------------------------
#define FLASH_SMEM_FLOATS (128*64 + 128*64 + 64*132 + 64*65)
#define FLASH_SMEM_BYTES  (FLASH_SMEM_FLOATS * 4)

__global__ __launch_bounds__(256) void flash_kernel(const float* __restrict__ Q,
                                                    const float* __restrict__ K,
                                                    const float* __restrict__ V,
                                                    float* __restrict__ Ot)
{
    extern __shared__ float sm[];
    float* Qt = sm;                    // 8192
    float* Kt = Qt + 128 * 64;         // 8192
    float* Vs = Kt + 128 * 64;         // 64*132
    float* Ps = Vs + 64 * 132;         // 64*65

    const int qb    = blockIdx.x;      // 0..31
    const int h     = blockIdx.y;      // 0..15
    const int b     = blockIdx.z;      // 0..1
    const int qbase = qb * 64;
    const int tid   = threadIdx.x;
    const int tr    = tid >> 4;        // 0..15
    const int tc    = tid & 15;        // 0..15

    const size_t rowbase = (size_t)b * S_;
    const int    colbase = h * DH_;

    // Load Q tile transposed: Qt[d][r]
#pragma unroll
    for (int it = 0; it < 8; it++) {
        int chunk = it * 256 + tid;
        int r  = chunk & 63;
        int d4 = chunk >> 6;           // 0..31
        float4 vq = *(const float4*)&Q[(rowbase + qbase + r) * DIM_ + colbase + d4 * 4];
        Qt[(d4 * 4 + 0) * 64 + r] = vq.x;
        Qt[(d4 * 4 + 1) * 64 + r] = vq.y;
        Qt[(d4 * 4 + 2) * 64 + r] = vq.z;
        Qt[(d4 * 4 + 3) * 64 + r] = vq.w;
    }

    float m_reg[4], l_reg[4], acc[4][8];
#pragma unroll
    for (int i = 0; i < 4; i++) {
        m_reg[i] = -1e30f;
        l_reg[i] = 0.f;
#pragma unroll
        for (int j = 0; j < 8; j++) acc[i][j] = 0.f;
    }

    const float sc = 0.08838834764831845f;   // 1/sqrt(128)

    for (int kb = 0; kb <= qb; kb++) {
        const int kbase = kb * 64;
        __syncthreads();   // protect Kt/Vs (prev iter PV) and Qt on first iter

        // Load K tile transposed
#pragma unroll
        for (int it = 0; it < 8; it++) {
            int chunk = it * 256 + tid;
            int r  = chunk & 63;
            int d4 = chunk >> 6;
            float4 vk = *(const float4*)&K[(rowbase + kbase + r) * DIM_ + colbase + d4 * 4];
            Kt[(d4 * 4 + 0) * 64 + r] = vk.x;
            Kt[(d4 * 4 + 1) * 64 + r] = vk.y;
            Kt[(d4 * 4 + 2) * 64 + r] = vk.z;
            Kt[(d4 * 4 + 3) * 64 + r] = vk.w;
        }
        // Load V tile natural
#pragma unroll
        for (int it = 0; it < 8; it++) {
            int chunk = it * 256 + tid;
            int j  = chunk >> 5;       // 0..63
            int c4 = chunk & 31;       // 0..31
            float4 vv = *(const float4*)&V[(rowbase + kbase + j) * DIM_ + colbase + c4 * 4];
            *(float4*)&Vs[j * 132 + c4 * 4] = vv;
        }
        __syncthreads();

        // S = Q @ K^T  (4x4 per thread: rows tr*4+i, cols tc*4+j)
        float sacc[4][4];
#pragma unroll
        for (int i = 0; i < 4; i++)
#pragma unroll
            for (int j = 0; j < 4; j++) sacc[i][j] = 0.f;

#pragma unroll 8
        for (int d = 0; d < 128; d++) {
            float4 qv = *(const float4*)&Qt[d * 64 + tr * 4];
            float4 kv = *(const float4*)&Kt[d * 64 + tc * 4];
            const float qa[4] = {qv.x, qv.y, qv.z, qv.w};
            const float ka[4] = {kv.x, kv.y, kv.z, kv.w};
#pragma unroll
            for (int i = 0; i < 4; i++)
#pragma unroll
                for (int j = 0; j < 4; j++)
                    sacc[i][j] = fmaf(qa[i], ka[j], sacc[i][j]);
        }

        // scale + causal mask + online softmax
        float p[4][4];
#pragma unroll
        for (int i = 0; i < 4; i++) {
            const int gr = qbase + tr * 4 + i;
            float tm = -1e30f;
#pragma unroll
            for (int j = 0; j < 4; j++) {
                const int gc = kbase + tc * 4 + j;
                float sv = (gc <= gr) ? sacc[i][j] * sc : -1e30f;
                sacc[i][j] = sv;
                tm = fmaxf(tm, sv);
            }
            // row max across the 16 threads sharing this row (lanes differ in tc)
            tm = fmaxf(tm, __shfl_xor_sync(0xffffffffu, tm, 1));
            tm = fmaxf(tm, __shfl_xor_sync(0xffffffffu, tm, 2));
            tm = fmaxf(tm, __shfl_xor_sync(0xffffffffu, tm, 4));
            tm = fmaxf(tm, __shfl_xor_sync(0xffffffffu, tm, 8));

            float mnew  = fmaxf(m_reg[i], tm);
            float alpha = __expf(m_reg[i] - mnew);
            float rs = 0.f;
#pragma unroll
            for (int j = 0; j < 4; j++) {
                p[i][j] = __expf(sacc[i][j] - mnew);
                rs += p[i][j];
            }
            rs += __shfl_xor_sync(0xffffffffu, rs, 1);
            rs += __shfl_xor_sync(0xffffffffu, rs, 2);
            rs += __shfl_xor_sync(0xffffffffu, rs, 4);
            rs += __shfl_xor_sync(0xffffffffu, rs, 8);

            l_reg[i] = alpha * l_reg[i] + rs;
            m_reg[i] = mnew;
#pragma unroll
            for (int cc = 0; cc < 8; cc++) acc[i][cc] *= alpha;
#pragma unroll
            for (int j = 0; j < 4; j++)
                Ps[(tr * 4 + i) * 65 + tc * 4 + j] = p[i][j];
        }
        __syncthreads();

        // O += P @ V   (rows tr*4+i, cols tc*8+cc)
#pragma unroll 4
        for (int j = 0; j < 64; j++) {
            float4 v0 = *(const float4*)&Vs[j * 132 + tc * 8];
            float4 v1 = *(const float4*)&Vs[j * 132 + tc * 8 + 4];
            const float va[8] = {v0.x, v0.y, v0.z, v0.w, v1.x, v1.y, v1.z, v1.w};
#pragma unroll
            for (int i = 0; i < 4; i++) {
                float pv = Ps[(tr * 4 + i) * 65 + j];
#pragma unroll
                for (int cc = 0; cc < 8; cc++)
                    acc[i][cc] = fmaf(pv, va[cc], acc[i][cc]);
            }
        }
    }

    // Epilogue: Ot[b, colbase + c, qbase + r] = acc / l
#pragma unroll
    for (int i = 0; i < 4; i++) {
        const float inv = 1.0f / l_reg[i];
        const int   r   = qbase + tr * 4 + i;
#pragma unroll
        for (int cc = 0; cc < 8; cc++) {
            const int c = colbase + tc * 8 + cc;
            Ot[((size_t)b * DIM_ + c) * S_ + r] = acc[i][cc] * inv;
        }
    }
}

// ---------------------------------------------------------------------------
// Launch
// ---------------------------------------------------------------------------
extern "C" void kernel_launch(void* const* d_in, const int* in_sizes, int n_in,
                              void* d_out, int out_size)
{
    const float* x    = (const float*)d_in[0];
    const float* Wq   = (const float*)d_in[1];
    const float* Wk   = (const float*)d_in[2];
    const float* Wv   = (const float*)d_in[3];
    const float* Wo   = (const float*)d_in[4];
    const float* cosb = (const float*)d_in[5];
    const float* sinb = (const float*)d_in[6];
    // d_in[7] = mask: causal handled analytically (-1e9 underflows to prob 0)

    float *q, *k, *v, *ot;
    cudaGetSymbolAddress((void**)&q,  g_q);
    cudaGetSymbolAddress((void**)&k,  g_k);
    cudaGetSymbolAddress((void**)&v,  g_v);
    cudaGetSymbolAddress((void**)&ot, g_ot);

    cudaFuncSetAttribute(flash_kernel, cudaFuncAttributeMaxDynamicSharedMemorySize,
                         FLASH_SMEM_BYTES);

    dim3 gproj(DIM_ / 128, MROWS / 128);   // (16, 32)

    // QKV projections: Q = X @ Wq^T, etc.
    sgemm_abt<<<gproj, 256>>>(x, Wq, q, MROWS, DIM_, DIM_);
    sgemm_abt<<<gproj, 256>>>(x, Wk, k, MROWS, DIM_, DIM_);
    sgemm_abt<<<gproj, 256>>>(x, Wv, v, MROWS, DIM_, DIM_);

    // RoPE in-place on q, k
    int npairs = MROWS * (DIM_ / 2);
    rope_kernel<<<npairs / 256, 256>>>(q, k, cosb, sinb);

    // Causal flash attention -> Ot[b, h*128+dh, s]
    dim3 gflash(S_ / 64, H_, B_);          // (32, 16, 2)
    flash_kernel<<<gflash, 256, FLASH_SMEM_BYTES>>>(q, k, v, ot);

    // Output projection: Out[b,p,e] = sum_s Ot[b,p,s] * Wo[e,s]
    sgemm_abt<<<gproj, 256>>>(ot, Wo, (float*)d_out, MROWS, DIM_, DIM_);
}

// round 3
// speedup vs baseline: 2.0323x; 2.0323x over previous
#include <cuda_runtime.h>
#include <cuda_bf16.h>
#include <cstdint>
#include <math.h>

// Problem constants
#define B_    2
#define S_    2048
#define DIM_  2048
#define H_    16
#define DH_   128
#define MROWS (B_ * S_)   // 4096

// ---------------------------------------------------------------------------
// Scratch (allocation-free rule: device globals)
// ---------------------------------------------------------------------------
__device__ float g_q [MROWS * DIM_];
__device__ float g_k [MROWS * DIM_];
__device__ float g_v [MROWS * DIM_];
__device__ float g_ot[MROWS * DIM_];

__device__ __nv_bfloat16 g_xhi [MROWS * DIM_];
__device__ __nv_bfloat16 g_xlo [MROWS * DIM_];
__device__ __nv_bfloat16 g_wqhi[DIM_ * DIM_];
__device__ __nv_bfloat16 g_wqlo[DIM_ * DIM_];
__device__ __nv_bfloat16 g_wkhi[DIM_ * DIM_];
__device__ __nv_bfloat16 g_wklo[DIM_ * DIM_];
__device__ __nv_bfloat16 g_wvhi[DIM_ * DIM_];
__device__ __nv_bfloat16 g_wvlo[DIM_ * DIM_];
__device__ __nv_bfloat16 g_wohi[DIM_ * DIM_];
__device__ __nv_bfloat16 g_wolo[DIM_ * DIM_];
__device__ __nv_bfloat16 g_othi[MROWS * DIM_];
__device__ __nv_bfloat16 g_otlo[MROWS * DIM_];

// ---------------------------------------------------------------------------
// Helpers
// ---------------------------------------------------------------------------
__device__ __forceinline__ uint32_t smem_u32(const void* p) {
    uint32_t a;
    asm("{ .reg .u64 t; cvta.to.shared.u64 t, %1; cvt.u32.u64 %0, t; }" : "=r"(a) : "l"(p));
    return a;
}
__device__ __forceinline__ void cp_async16(uint32_t dst, const void* src) {
    asm volatile("cp.async.cg.shared.global [%0], [%1], 16;" :: "r"(dst), "l"(src));
}
#define CP_COMMIT() asm volatile("cp.async.commit_group;" ::: "memory")
#define CP_WAIT(n)  asm volatile("cp.async.wait_group %0;" :: "n"(n) : "memory")

__device__ __forceinline__ void ldmatrix_x4(uint32_t& r0, uint32_t& r1,
                                            uint32_t& r2, uint32_t& r3, uint32_t addr) {
    asm volatile("ldmatrix.sync.aligned.m8n8.x4.shared.b16 {%0,%1,%2,%3}, [%4];"
                 : "=r"(r0), "=r"(r1), "=r"(r2), "=r"(r3) : "r"(addr));
}
__device__ __forceinline__ void mma_bf16(float* c, const uint32_t* a, const uint32_t* b) {
    asm volatile(
        "mma.sync.aligned.m16n8k16.row.col.f32.bf16.bf16.f32 "
        "{%0,%1,%2,%3}, {%4,%5,%6,%7}, {%8,%9}, {%0,%1,%2,%3};"
        : "+f"(c[0]), "+f"(c[1]), "+f"(c[2]), "+f"(c[3])
        : "r"(a[0]), "r"(a[1]), "r"(a[2]), "r"(a[3]), "r"(b[0]), "r"(b[1]));
}

// ---------------------------------------------------------------------------
// Split fp32 -> (bf16 hi, bf16 lo). Vectorized by 4.
// ---------------------------------------------------------------------------
__global__ void split_kernel(const float* __restrict__ in,
                             __nv_bfloat16* __restrict__ hi,
                             __nv_bfloat16* __restrict__ lo, int n4)
{
    int i = blockIdx.x * blockDim.x + threadIdx.x;
    if (i >= n4) return;
    float4 v = ((const float4*)in)[i];
    __nv_bfloat16 h0 = __float2bfloat16(v.x);
    __nv_bfloat16 h1 = __float2bfloat16(v.y);
    __nv_bfloat16 h2 = __float2bfloat16(v.z);
    __nv_bfloat16 h3 = __float2bfloat16(v.w);
    __nv_bfloat16 l0 = __float2bfloat16(v.x - __bfloat162float(h0));
    __nv_bfloat16 l1 = __float2bfloat16(v.y - __bfloat162float(h1));
    __nv_bfloat16 l2 = __float2bfloat16(v.z - __bfloat162float(h2));
    __nv_bfloat16 l3 = __float2bfloat16(v.w - __bfloat162float(h3));
    ((__nv_bfloat162*)hi)[2 * i]     = __nv_bfloat162(h0, h1);
    ((__nv_bfloat162*)hi)[2 * i + 1] = __nv_bfloat162(h2, h3);
    ((__nv_bfloat162*)lo)[2 * i]     = __nv_bfloat162(l0, l1);
    ((__nv_bfloat162*)lo)[2 * i + 1] = __nv_bfloat162(l2, l3);
}

// ---------------------------------------------------------------------------
// mma.sync GEMM:  C[M,N] = sum of 3 segments Aseg[M,K] @ Bseg[N,K]^T
// segments (Ahi,Bhi),(Alo,Bhi),(Ahi,Blo) accumulated in fp32 registers.
// Block 128x128, BK=32, 256 threads (8 warps = 4M x 2N, warp tile 32x64).
// 2-stage cp.async pipeline; XOR-swizzled smem (conflict-free ldmatrix).
// ---------------------------------------------------------------------------
#define GBM 128
#define GBN 128
#define GBK 32
// smem tile: 128 rows x 32 bf16 = 64B/row; chunk = 16B; phys_chunk = c ^ ((r>>1)&3)
__device__ __forceinline__ uint32_t sw_off(int r, int c) {
    return (uint32_t)(r * 64 + ((c ^ ((r >> 1) & 3)) << 4));
}

__global__ __launch_bounds__(256, 2) void gemm_mma_bf16x3(
    const __nv_bfloat16* __restrict__ Ahi, const __nv_bfloat16* __restrict__ Alo,
    const __nv_bfloat16* __restrict__ Bhi, const __nv_bfloat16* __restrict__ Blo,
    float* __restrict__ C, int M, int N, int K)
{
    __shared__ __align__(1024) char sm[4 * 8192];   // A[2], B[2] stages

    const int tid  = threadIdx.x;
    const int wid  = tid >> 5;
    const int lane = tid & 31;
    const int bm = blockIdx.y * GBM;
    const int bn = blockIdx.x * GBN;

    const int wm = wid & 3;          // 0..3  -> M offset 32*wm
    const int wn = wid >> 2;         // 0..1  -> N offset 64*wn
    const int mbase = wm * 32;
    const int nbase = wn * 64;

    const uint32_t sA[2] = { smem_u32(sm),         smem_u32(sm + 8192)  };
    const uint32_t sB[2] = { smem_u32(sm + 16384), smem_u32(sm + 24576) };

    const __nv_bfloat16* Asegs[3] = {Ahi, Alo, Ahi};
    const __nv_bfloat16* Bsegs[3] = {Bhi, Bhi, Blo};

    const int NIT = 3 * (K / GBK);   // 192 for K=2048

    // load thread mapping: id -> row = id>>2, chunk = id&3 (16B each)
    const int lr0 = tid >> 2;        // rows tid/4 and tid/4+64
    const int lc  = tid & 3;

    auto issue = [&](int it, int buf) {
        const int seg = it >> 6;               // K/GBK = 64 iters per segment
        const int k0  = (it & 63) * GBK;
        const __nv_bfloat16* A = Asegs[seg];
        const __nv_bfloat16* Bp = Bsegs[seg];
#pragma unroll
        for (int i = 0; i < 2; i++) {
            int r = lr0 + i * 64;
            uint32_t off = sw_off(r, lc);
            cp_async16(sA[buf] + off, A  + (size_t)(bm + r) * K + k0 + lc * 8);
            cp_async16(sB[buf] + off, Bp + (size_t)(bn + r) * K + k0 + lc * 8);
        }
        CP_COMMIT();
    };

    float acc[2][8][4];
#pragma unroll
    for (int mt = 0; mt < 2; mt++)
#pragma unroll
        for (int nt = 0; nt < 8; nt++)
#pragma unroll
            for (int e = 0; e < 4; e++) acc[mt][nt][e] = 0.f;

    issue(0, 0);

    for (int it = 0; it < NIT; it++) {
        const int buf = it & 1;
        if (it + 1 < NIT) {
            issue(it + 1, buf ^ 1);
            CP_WAIT(1);
        } else {
            CP_WAIT(0);
        }
        __syncthreads();

#pragma unroll
        for (int ks = 0; ks < 2; ks++) {
            // A fragments: 2 m16 tiles
            uint32_t afr[2][4];
#pragma unroll
            for (int mt = 0; mt < 2; mt++) {
                int row   = mbase + mt * 16 + (lane & 15);
                int chunk = ks * 2 + (lane >> 4);
                ldmatrix_x4(afr[mt][0], afr[mt][1], afr[mt][2], afr[mt][3],
                            sA[buf] + sw_off(row, chunk));
            }
            // B fragments: 8 n8 tiles via 4 x4-loads
            uint32_t bfr[8][2];
#pragma unroll
            for (int nt2 = 0; nt2 < 4; nt2++) {
                int row   = nbase + nt2 * 16 + ((lane >> 4) << 3) + (lane & 7);
                int chunk = ks * 2 + ((lane >> 3) & 1);
                ldmatrix_x4(bfr[nt2 * 2][0], bfr[nt2 * 2][1],
                            bfr[nt2 * 2 + 1][0], bfr[nt2 * 2 + 1][1],
                            sB[buf] + sw_off(row, chunk));
            }
#pragma unroll
            for (int mt = 0; mt < 2; mt++)
#pragma unroll
                for (int nt = 0; nt < 8; nt++)
                    mma_bf16(acc[mt][nt], afr[mt], bfr[nt]);
        }
        __syncthreads();
    }

    // Epilogue: c0,c1 at (row, col..col+1), c2,c3 at (row+8, col..col+1)
    const int erow = lane >> 2;
    const int ecol = (lane & 3) * 2;
#pragma unroll
    for (int mt = 0; mt < 2; mt++) {
#pragma unroll
        for (int nt = 0; nt < 8; nt++) {
            float* cp0 = C + (size_t)(bm + mbase + mt * 16 + erow) * N
                           + bn + nbase + nt * 8 + ecol;
            *(float2*)cp0              = make_float2(acc[mt][nt][0], acc[mt][nt][1]);
            *(float2*)(cp0 + 8 * N)    = make_float2(acc[mt][nt][2], acc[mt][nt][3]);
        }
    }
}

// ---------------------------------------------------------------------------
// RoPE: in-place on Q and K.
// ---------------------------------------------------------------------------
__global__ void rope_kernel(float* __restrict__ q, float* __restrict__ k,
                            const float* __restrict__ cosb,
                            const float* __restrict__ sinb)
{
    int idx = blockIdx.x * blockDim.x + threadIdx.x;
    int row = idx >> 10;
    int pp  = idx & 1023;
    int i   = pp & 63;
    int hh  = pp >> 6;
    int col = (hh << 7) + (i << 1);
    int s   = row & (S_ - 1);

    float c  = cosb[s * 64 + i];
    float sn = sinb[s * 64 + i];

    size_t off = (size_t)row * DIM_ + col;
    float2 qv = *(float2*)(q + off);
    float2 kv = *(float2*)(k + off);
    *(float2*)(q + off) = make_float2(qv.x * c - qv.y * sn, qv.x * sn + qv.y * c);
    *(float2*)(k + off) = make_float2(kv.x * c - kv.y * sn, kv.x * sn + kv.y * c);
}

// ---------------------------------------------------------------------------
// Flash attention, fp32, causal. TQ=TK=64, DH=128, 256 threads.
// Writes O transposed: Ot[b, h*128 + dh, s]
// ---------------------------------------------------------------------------
#define FLASH_SMEM_FLOATS (128*64 + 128*64 + 64*132 + 64*65)
#define FLASH_SMEM_BYTES  (FLASH_SMEM_FLOATS * 4)

__global__ __launch_bounds__(256) void flash_kernel(const float* __restrict__ Q,
                                                    const float* __restrict__ K,
                                                    const float* __restrict__ V,
                                                    float* __restrict__ Ot)
{
    extern __shared__ float smf[];
    float* Qt = smf;
    float* Kt = Qt + 128 * 64;
    float* Vs = Kt + 128 * 64;
    float* Ps = Vs + 64 * 132;

    const int qb    = blockIdx.x;
    const int h     = blockIdx.y;
    const int b     = blockIdx.z;
    const int qbase = qb * 64;
    const int tid   = threadIdx.x;
    const int tr    = tid >> 4;
    const int tc    = tid & 15;

    const size_t rowbase = (size_t)b * S_;
    const int    colbase = h * DH_;

#pragma unroll
    for (int it = 0; it < 8; it++) {
        int chunk = it * 256 + tid;
        int r  = chunk & 63;
        int d4 = chunk >> 6;
        float4 vq = *(const float4*)&Q[(rowbase + qbase + r) * DIM_ + colbase + d4 * 4];
        Qt[(d4 * 4 + 0) * 64 + r] = vq.x;
        Qt[(d4 * 4 + 1) * 64 + r] = vq.y;
        Qt[(d4 * 4 + 2) * 64 + r] = vq.z;
        Qt[(d4 * 4 + 3) * 64 + r] = vq.w;
    }

    float m_reg[4], l_reg[4], acc[4][8];
#pragma unroll
    for (int i = 0; i < 4; i++) {
        m_reg[i] = -1e30f;
        l_reg[i] = 0.f;
#pragma unroll
        for (int j = 0; j < 8; j++) acc[i][j] = 0.f;
    }

    const float sc = 0.08838834764831845f;

    for (int kb = 0; kb <= qb; kb++) {
        const int kbase = kb * 64;
        __syncthreads();

#pragma unroll
        for (int it = 0; it < 8; it++) {
            int chunk = it * 256 + tid;
            int r  = chunk & 63;
            int d4 = chunk >> 6;
            float4 vk = *(const float4*)&K[(rowbase + kbase + r) * DIM_ + colbase + d4 * 4];
            Kt[(d4 * 4 + 0) * 64 + r] = vk.x;
            Kt[(d4 * 4 + 1) * 64 + r] = vk.y;
            Kt[(d4 * 4 + 2) * 64 + r] = vk.z;
            Kt[(d4 * 4 + 3) * 64 + r] = vk.w;
        }
#pragma unroll
        for (int it = 0; it < 8; it++) {
            int chunk = it * 256 + tid;
            int j  = chunk >> 5;
            int c4 = chunk & 31;
            float4 vv = *(const float4*)&V[(rowbase + kbase + j) * DIM_ + colbase + c4 * 4];
            *(float4*)&Vs[j * 132 + c4 * 4] = vv;
        }
        __syncthreads();

        float sacc[4][4];
#pragma unroll
        for (int i = 0; i < 4; i++)
#pragma unroll
            for (int j = 0; j < 4; j++) sacc[i][j] = 0.f;

#pragma unroll 8
        for (int d = 0; d < 128; d++) {
            float4 qv = *(const float4*)&Qt[d * 64 + tr * 4];
            float4 kv = *(const float4*)&Kt[d * 64 + tc * 4];
            const float qa[4] = {qv.x, qv.y, qv.z, qv.w};
            const float ka[4] = {kv.x, kv.y, kv.z, kv.w};
#pragma unroll
            for (int i = 0; i < 4; i++)
#pragma unroll
                for (int j = 0; j < 4; j++)
                    sacc[i][j] = fmaf(qa[i], ka[j], sacc[i][j]);
        }

        float p[4][4];
#pragma unroll
        for (int i = 0; i < 4; i++) {
            const int gr = qbase + tr * 4 + i;
            float tm = -1e30f;
#pragma unroll
            for (int j = 0; j < 4; j++) {
                const int gc = kbase + tc * 4 + j;
                float sv = (gc <= gr) ? sacc[i][j] * sc : -1e30f;
                sacc[i][j] = sv;
                tm = fmaxf(tm, sv);
            }
            tm = fmaxf(tm, __shfl_xor_sync(0xffffffffu, tm, 1));
            tm = fmaxf(tm, __shfl_xor_sync(0xffffffffu, tm, 2));
            tm = fmaxf(tm, __shfl_xor_sync(0xffffffffu, tm, 4));
            tm = fmaxf(tm, __shfl_xor_sync(0xffffffffu, tm, 8));

            float mnew  = fmaxf(m_reg[i], tm);
            float alpha = __expf(m_reg[i] - mnew);
            float rs = 0.f;
#pragma unroll
            for (int j = 0; j < 4; j++) {
                p[i][j] = __expf(sacc[i][j] - mnew);
                rs += p[i][j];
            }
            rs += __shfl_xor_sync(0xffffffffu, rs, 1);
            rs += __shfl_xor_sync(0xffffffffu, rs, 2);
            rs += __shfl_xor_sync(0xffffffffu, rs, 4);
            rs += __shfl_xor_sync(0xffffffffu, rs, 8);

            l_reg[i] = alpha * l_reg[i] + rs;
            m_reg[i] = mnew;
#pragma unroll
            for (int cc = 0; cc < 8; cc++) acc[i][cc] *= alpha;
#pragma unroll
            for (int j = 0; j < 4; j++)
                Ps[(tr * 4 + i) * 65 + tc * 4 + j] = p[i][j];
        }
        __syncthreads();

#pragma unroll 4
        for (int j = 0; j < 64; j++) {
            float4 v0 = *(const float4*)&Vs[j * 132 + tc * 8];
            float4 v1 = *(const float4*)&Vs[j * 132 + tc * 8 + 4];
            const float va[8] = {v0.x, v0.y, v0.z, v0.w, v1.x, v1.y, v1.z, v1.w};
#pragma unroll
            for (int i = 0; i < 4; i++) {
                float pv = Ps[(tr * 4 + i) * 65 + j];
#pragma unroll
                for (int cc = 0; cc < 8; cc++)
                    acc[i][cc] = fmaf(pv, va[cc], acc[i][cc]);
            }
        }
    }

#pragma unroll
    for (int i = 0; i < 4; i++) {
        const float inv = 1.0f / l_reg[i];
        const int   r   = qbase + tr * 4 + i;
#pragma unroll
        for (int cc = 0; cc < 8; cc++) {
            const int c = colbase + tc * 8 + cc;
            Ot[((size_t)b * DIM_ + c) * S_ + r] = acc[i][cc] * inv;
        }
    }
}

// ---------------------------------------------------------------------------
// Launch
// ---------------------------------------------------------------------------
extern "C" void kernel_launch(void* const* d_in, const int* in_sizes, int n_in,
                              void* d_out, int out_size)
{
    const float* x    = (const float*)d_in[0];
    const float* Wq   = (const float*)d_in[1];
    const float* Wk   = (const float*)d_in[2];
    const float* Wv   = (const float*)d_in[3];
    const float* Wo   = (const float*)d_in[4];
    const float* cosb = (const float*)d_in[5];
    const float* sinb = (const float*)d_in[6];
    // d_in[7] = mask: causal handled analytically

    float *q, *k, *v, *ot;
    cudaGetSymbolAddress((void**)&q,  g_q);
    cudaGetSymbolAddress((void**)&k,  g_k);
    cudaGetSymbolAddress((void**)&v,  g_v);
    cudaGetSymbolAddress((void**)&ot, g_ot);

    __nv_bfloat16 *xhi, *xlo, *wqhi, *wqlo, *wkhi, *wklo, *wvhi, *wvlo, *wohi, *wolo, *othi, *otlo;
    cudaGetSymbolAddress((void**)&xhi,  g_xhi);
    cudaGetSymbolAddress((void**)&xlo,  g_xlo);
    cudaGetSymbolAddress((void**)&wqhi, g_wqhi);
    cudaGetSymbolAddress((void**)&wqlo, g_wqlo);
    cudaGetSymbolAddress((void**)&wkhi, g_wkhi);
    cudaGetSymbolAddress((void**)&wklo, g_wklo);
    cudaGetSymbolAddress((void**)&wvhi, g_wvhi);
    cudaGetSymbolAddress((void**)&wvlo, g_wvlo);
    cudaGetSymbolAddress((void**)&wohi, g_wohi);
    cudaGetSymbolAddress((void**)&wolo, g_wolo);
    cudaGetSymbolAddress((void**)&othi, g_othi);
    cudaGetSymbolAddress((void**)&otlo, g_otlo);

    cudaFuncSetAttribute(flash_kernel, cudaFuncAttributeMaxDynamicSharedMemorySize,
                         FLASH_SMEM_BYTES);

    // Split inputs into bf16 hi/lo
    {
        int n4x = MROWS * DIM_ / 4;
        int n4w = DIM_ * DIM_ / 4;
        split_kernel<<<n4x / 256, 256>>>(x,  xhi,  xlo,  n4x);
        split_kernel<<<n4w / 256, 256>>>(Wq, wqhi, wqlo, n4w);
        split_kernel<<<n4w / 256, 256>>>(Wk, wkhi, wklo, n4w);
        split_kernel<<<n4w / 256, 256>>>(Wv, wvhi, wvlo, n4w);
        split_kernel<<<n4w / 256, 256>>>(Wo, wohi, wolo, n4w);
    }

    dim3 ggemm(DIM_ / GBN, MROWS / GBM);   // (16, 32)

    // QKV projections on tensor cores (bf16x3 split ~ fp32 accuracy)
    gemm_mma_bf16x3<<<ggemm, 256>>>(xhi, xlo, wqhi, wqlo, q, MROWS, DIM_, DIM_);
    gemm_mma_bf16x3<<<ggemm, 256>>>(xhi, xlo, wkhi, wklo, k, MROWS, DIM_, DIM_);
    gemm_mma_bf16x3<<<ggemm, 256>>>(xhi, xlo, wvhi, wvlo, v, MROWS, DIM_, DIM_);

    // RoPE in-place on q, k
    int npairs = MROWS * (DIM_ / 2);
    rope_kernel<<<npairs / 256, 256>>>(q, k, cosb, sinb);

    // Causal flash attention -> Ot[b, h*128+dh, s]
    dim3 gflash(S_ / 64, H_, B_);
    flash_kernel<<<gflash, 256, FLASH_SMEM_BYTES>>>(q, k, v, ot);

    // Split Ot, then output projection on tensor cores
    {
        int n4o = MROWS * DIM_ / 4;
        split_kernel<<<n4o / 256, 256>>>(ot, othi, otlo, n4o);
    }
    gemm_mma_bf16x3<<<ggemm, 256>>>(othi, otlo, wohi, wolo, (float*)d_out,
                                    MROWS, DIM_, DIM_);
}

// round 4
// speedup vs baseline: 3.4667x; 1.7058x over previous
#include <cuda_runtime.h>
#include <cuda_bf16.h>
#include <cstdint>
#include <math.h>

// Problem constants
#define B_    2
#define S_    2048
#define DIM_  2048
#define H_    16
#define DH_   128
#define MROWS (B_ * S_)   // 4096

// ---------------------------------------------------------------------------
// Scratch (allocation-free rule: device globals)
// ---------------------------------------------------------------------------
__device__ float g_q [MROWS * DIM_];
__device__ float g_k [MROWS * DIM_];
__device__ float g_v [MROWS * DIM_];

__device__ __nv_bfloat16 g_xhi [MROWS * DIM_];
__device__ __nv_bfloat16 g_xlo [MROWS * DIM_];
__device__ __nv_bfloat16 g_wqhi[DIM_ * DIM_];
__device__ __nv_bfloat16 g_wqlo[DIM_ * DIM_];
__device__ __nv_bfloat16 g_wkhi[DIM_ * DIM_];
__device__ __nv_bfloat16 g_wklo[DIM_ * DIM_];
__device__ __nv_bfloat16 g_wvhi[DIM_ * DIM_];
__device__ __nv_bfloat16 g_wvlo[DIM_ * DIM_];
__device__ __nv_bfloat16 g_wohi[DIM_ * DIM_];
__device__ __nv_bfloat16 g_wolo[DIM_ * DIM_];
__device__ __nv_bfloat16 g_qhi [MROWS * DIM_];
__device__ __nv_bfloat16 g_qlo [MROWS * DIM_];
__device__ __nv_bfloat16 g_khi [MROWS * DIM_];
__device__ __nv_bfloat16 g_klo [MROWS * DIM_];
__device__ __nv_bfloat16 g_vhi [MROWS * DIM_];
__device__ __nv_bfloat16 g_vlo [MROWS * DIM_];
__device__ __nv_bfloat16 g_othi[MROWS * DIM_];
__device__ __nv_bfloat16 g_otlo[MROWS * DIM_];

// ---------------------------------------------------------------------------
// Helpers
// ---------------------------------------------------------------------------
__device__ __forceinline__ uint32_t smem_u32(const void* p) {
    uint32_t a;
    asm("{ .reg .u64 t; cvta.to.shared.u64 t, %1; cvt.u32.u64 %0, t; }" : "=r"(a) : "l"(p));
    return a;
}
__device__ __forceinline__ void cp_async16(uint32_t dst, const void* src) {
    asm volatile("cp.async.cg.shared.global [%0], [%1], 16;" :: "r"(dst), "l"(src));
}
#define CP_COMMIT() asm volatile("cp.async.commit_group;" ::: "memory")
#define CP_WAIT(n)  asm volatile("cp.async.wait_group %0;" :: "n"(n) : "memory")

__device__ __forceinline__ void ldmatrix_x4(uint32_t& r0, uint32_t& r1,
                                            uint32_t& r2, uint32_t& r3, uint32_t addr) {
    asm volatile("ldmatrix.sync.aligned.m8n8.x4.shared.b16 {%0,%1,%2,%3}, [%4];"
                 : "=r"(r0), "=r"(r1), "=r"(r2), "=r"(r3) : "r"(addr));
}
__device__ __forceinline__ void ldmatrix_x4_trans(uint32_t& r0, uint32_t& r1,
                                                  uint32_t& r2, uint32_t& r3, uint32_t addr) {
    asm volatile("ldmatrix.sync.aligned.m8n8.x4.trans.shared.b16 {%0,%1,%2,%3}, [%4];"
                 : "=r"(r0), "=r"(r1), "=r"(r2), "=r"(r3) : "r"(addr));
}
__device__ __forceinline__ void mma_bf16(float* c, const uint32_t* a, const uint32_t* b) {
    asm volatile(
        "mma.sync.aligned.m16n8k16.row.col.f32.bf16.bf16.f32 "
        "{%0,%1,%2,%3}, {%4,%5,%6,%7}, {%8,%9}, {%0,%1,%2,%3};"
        : "+f"(c[0]), "+f"(c[1]), "+f"(c[2]), "+f"(c[3])
        : "r"(a[0]), "r"(a[1]), "r"(a[2]), "r"(a[3]), "r"(b[0]), "r"(b[1]));
}

// Fast exp2 for x <= 0 (degree-5 poly on FMA pipe, avoids MUFU bottleneck)
__device__ __forceinline__ float fexp2(float x) {
    x = fmaxf(x, -80.f);
    float f = x + 12582912.f;                  // round-to-nearest-int magic
    int  n  = __float_as_int(f) - 0x4B400000;
    float r = x - (f - 12582912.f);            // r in [-0.5, 0.5]
    float p =            1.3333558146e-3f;
    p = fmaf(p, r, 9.6181291076e-3f);
    p = fmaf(p, r, 5.5504108665e-2f);
    p = fmaf(p, r, 2.4022650696e-1f);
    p = fmaf(p, r, 6.9314718056e-1f);
    p = fmaf(p, r, 1.0f);
    return __int_as_float(__float_as_int(p) + (n << 23));
}

__device__ __forceinline__ void split_pack(float x, float y, uint32_t& hi, uint32_t& lo) {
    __nv_bfloat162 h = __float22bfloat162_rn(make_float2(x, y));
    float2 hb = __bfloat1622float2(h);
    __nv_bfloat162 l = __float22bfloat162_rn(make_float2(x - hb.x, y - hb.y));
    hi = *(uint32_t*)&h;
    lo = *(uint32_t*)&l;
}

// ---------------------------------------------------------------------------
// Split fp32 -> (bf16 hi, bf16 lo). Vectorized by 4.
// ---------------------------------------------------------------------------
__global__ void split_kernel(const float* __restrict__ in,
                             __nv_bfloat16* __restrict__ hi,
                             __nv_bfloat16* __restrict__ lo, int n4)
{
    int i = blockIdx.x * blockDim.x + threadIdx.x;
    if (i >= n4) return;
    float4 v = ((const float4*)in)[i];
    uint32_t h0, l0, h1, l1;
    split_pack(v.x, v.y, h0, l0);
    split_pack(v.z, v.w, h1, l1);
    ((uint32_t*)hi)[2 * i]     = h0;
    ((uint32_t*)hi)[2 * i + 1] = h1;
    ((uint32_t*)lo)[2 * i]     = l0;
    ((uint32_t*)lo)[2 * i + 1] = l1;
}

// ---------------------------------------------------------------------------
// mma.sync GEMM (unchanged from R3):  C = sum of 3 bf16 segments A@B^T
// ---------------------------------------------------------------------------
#define GBM 128
#define GBN 128
#define GBK 32
__device__ __forceinline__ uint32_t sw_off(int r, int c) {
    return (uint32_t)(r * 64 + ((c ^ ((r >> 1) & 3)) << 4));
}

__global__ __launch_bounds__(256, 2) void gemm_mma_bf16x3(
    const __nv_bfloat16* __restrict__ Ahi, const __nv_bfloat16* __restrict__ Alo,
    const __nv_bfloat16* __restrict__ Bhi, const __nv_bfloat16* __restrict__ Blo,
    float* __restrict__ C, int M, int N, int K)
{
    __shared__ __align__(1024) char sm[4 * 8192];

    const int tid  = threadIdx.x;
    const int wid  = tid >> 5;
    const int lane = tid & 31;
    const int bm = blockIdx.y * GBM;
    const int bn = blockIdx.x * GBN;

    const int wm = wid & 3;
    const int wn = wid >> 2;
    const int mbase = wm * 32;
    const int nbase = wn * 64;

    const uint32_t sA[2] = { smem_u32(sm),         smem_u32(sm + 8192)  };
    const uint32_t sB[2] = { smem_u32(sm + 16384), smem_u32(sm + 24576) };

    const __nv_bfloat16* Asegs[3] = {Ahi, Alo, Ahi};
    const __nv_bfloat16* Bsegs[3] = {Bhi, Bhi, Blo};

    const int NIT = 3 * (K / GBK);

    const int lr0 = tid >> 2;
    const int lc  = tid & 3;

    auto issue = [&](int it, int buf) {
        const int seg = it >> 6;
        const int k0  = (it & 63) * GBK;
        const __nv_bfloat16* A = Asegs[seg];
        const __nv_bfloat16* Bp = Bsegs[seg];
#pragma unroll
        for (int i = 0; i < 2; i++) {
            int r = lr0 + i * 64;
            uint32_t off = sw_off(r, lc);
            cp_async16(sA[buf] + off, A  + (size_t)(bm + r) * K + k0 + lc * 8);
            cp_async16(sB[buf] + off, Bp + (size_t)(bn + r) * K + k0 + lc * 8);
        }
        CP_COMMIT();
    };

    float acc[2][8][4];
#pragma unroll
    for (int mt = 0; mt < 2; mt++)
#pragma unroll
        for (int nt = 0; nt < 8; nt++)
#pragma unroll
            for (int e = 0; e < 4; e++) acc[mt][nt][e] = 0.f;

    issue(0, 0);

    for (int it = 0; it < NIT; it++) {
        const int buf = it & 1;
        if (it + 1 < NIT) {
            issue(it + 1, buf ^ 1);
            CP_WAIT(1);
        } else {
            CP_WAIT(0);
        }
        __syncthreads();

#pragma unroll
        for (int ks = 0; ks < 2; ks++) {
            uint32_t afr[2][4];
#pragma unroll
            for (int mt = 0; mt < 2; mt++) {
                int row   = mbase + mt * 16 + (lane & 15);
                int chunk = ks * 2 + (lane >> 4);
                ldmatrix_x4(afr[mt][0], afr[mt][1], afr[mt][2], afr[mt][3],
                            sA[buf] + sw_off(row, chunk));
            }
            uint32_t bfr[8][2];
#pragma unroll
            for (int nt2 = 0; nt2 < 4; nt2++) {
                int row   = nbase + nt2 * 16 + ((lane >> 4) << 3) + (lane & 7);
                int chunk = ks * 2 + ((lane >> 3) & 1);
                ldmatrix_x4(bfr[nt2 * 2][0], bfr[nt2 * 2][1],
                            bfr[nt2 * 2 + 1][0], bfr[nt2 * 2 + 1][1],
                            sB[buf] + sw_off(row, chunk));
            }
#pragma unroll
            for (int mt = 0; mt < 2; mt++)
#pragma unroll
                for (int nt = 0; nt < 8; nt++)
                    mma_bf16(acc[mt][nt], afr[mt], bfr[nt]);
        }
        __syncthreads();
    }

    const int erow = lane >> 2;
    const int ecol = (lane & 3) * 2;
#pragma unroll
    for (int mt = 0; mt < 2; mt++) {
#pragma unroll
        for (int nt = 0; nt < 8; nt++) {
            float* cp0 = C + (size_t)(bm + mbase + mt * 16 + erow) * N
                           + bn + nbase + nt * 8 + ecol;
            *(float2*)cp0           = make_float2(acc[mt][nt][0], acc[mt][nt][1]);
            *(float2*)(cp0 + 8 * N) = make_float2(acc[mt][nt][2], acc[mt][nt][3]);
        }
    }
}

// ---------------------------------------------------------------------------
// RoPE + split: read fp32 q,k; rotate; write bf16 hi/lo (no fp32 writeback)
// ---------------------------------------------------------------------------
__global__ void rope_split(const float* __restrict__ q, const float* __restrict__ k,
                           const float* __restrict__ cosb, const float* __restrict__ sinb,
                           __nv_bfloat16* __restrict__ qhi, __nv_bfloat16* __restrict__ qlo,
                           __nv_bfloat16* __restrict__ khi, __nv_bfloat16* __restrict__ klo)
{
    int idx = blockIdx.x * blockDim.x + threadIdx.x;
    int row = idx >> 10;
    int pp  = idx & 1023;
    int i   = pp & 63;
    int hh  = pp >> 6;
    int col = (hh << 7) + (i << 1);
    int s   = row & (S_ - 1);

    float c  = cosb[s * 64 + i];
    float sn = sinb[s * 64 + i];

    size_t off = (size_t)row * DIM_ + col;
    float2 qv = *(const float2*)(q + off);
    float2 kv = *(const float2*)(k + off);
    float qr = qv.x * c - qv.y * sn, qi = qv.x * sn + qv.y * c;
    float kr = kv.x * c - kv.y * sn, ki = kv.x * sn + kv.y * c;

    uint32_t h, l;
    split_pack(qr, qi, h, l);
    *(uint32_t*)(qhi + off) = h;
    *(uint32_t*)(qlo + off) = l;
    split_pack(kr, ki, h, l);
    *(uint32_t*)(khi + off) = h;
    *(uint32_t*)(klo + off) = l;
}

// ---------------------------------------------------------------------------
// Flash attention on tensor cores (FA2 layout, bf16x3 QK and PV).
// CTA: 64 q-rows, 4 warps (16 rows each), kv tiles of 64, DH=128.
// smem: Qhi,Qlo,Khi,Klo,Vhi,Vlo tiles 64x128 bf16 each (16KB x6 = 96KB).
// Swizzle: row 256B = 16 chunks of 16B; phys chunk = c ^ (r & 7).
// Writes othi/otlo transposed: Ot[b, h*128+dh, s].
// ---------------------------------------------------------------------------
#define FL_SMEM 98304

__device__ __forceinline__ uint32_t fl_off(int r, int c) {
    return (uint32_t)(r * 256 + ((c ^ (r & 7)) << 4));
}

__global__ __launch_bounds__(128, 2) void flash_mma(
    const __nv_bfloat16* __restrict__ qhi, const __nv_bfloat16* __restrict__ qlo,
    const __nv_bfloat16* __restrict__ khi, const __nv_bfloat16* __restrict__ klo,
    const __nv_bfloat16* __restrict__ vhi, const __nv_bfloat16* __restrict__ vlo,
    __nv_bfloat16* __restrict__ othi, __nv_bfloat16* __restrict__ otlo)
{
    extern __shared__ __align__(1024) char sm8[];
    const uint32_t sQh = smem_u32(sm8);
    const uint32_t sQl = sQh + 16384;
    const uint32_t sKh = sQh + 32768;
    const uint32_t sKl = sQh + 49152;
    const uint32_t sVh = sQh + 65536;
    const uint32_t sVl = sQh + 81920;

    const int qb = blockIdx.x, h = blockIdx.y, b = blockIdx.z;
    const int qbase = qb * 64;
    const int tid = threadIdx.x, wid = tid >> 5, lane = tid & 31;
    const int mbase = wid * 16;
    const int colbase = h * DH_;
    const size_t rowg0 = ((size_t)b * S_ + qbase) * DIM_ + colbase;

    // Q tiles (hi+lo) via cp.async
#pragma unroll
    for (int i = 0; i < 8; i++) {
        int idx = i * 128 + tid;
        int r = idx >> 4, c = idx & 15;
        uint32_t off = fl_off(r, c);
        size_t g = rowg0 + (size_t)r * DIM_ + c * 8;
        cp_async16(sQh + off, qhi + g);
        cp_async16(sQl + off, qlo + g);
    }
    CP_COMMIT();

    float m0 = -1e30f, m1 = -1e30f, l0 = 0.f, l1 = 0.f;
    float o[16][4];
#pragma unroll
    for (int nt = 0; nt < 16; nt++)
#pragma unroll
        for (int e = 0; e < 4; e++) o[nt][e] = 0.f;

    const int rA = lane >> 2;        // 0..7
    const int cq = (lane & 3) * 2;   // 0,2,4,6
    const float KARG = 0.1275166782f;   // (1/sqrt(128)) * log2(e)

    // ldmatrix address components (within-warp)
    const int a_r  = (lane & 7) + ((lane >> 3) & 1) * 8;   // A/V row part
    const int a_cb = lane >> 4;                            // chunk bit
    const int bk_r = (lane & 7);                           // K b-frag row part
    const int bk_np = lane >> 4;                           // ntile select bit
    const int bk_cb = (lane >> 3) & 1;                     // chunk bit

    for (int kb = 0; kb <= qb; kb++) {
        const size_t krow0 = ((size_t)b * S_ + kb * 64) * DIM_ + colbase;
        __syncthreads();                 // previous iter fully consumed
#pragma unroll
        for (int i = 0; i < 8; i++) {
            int idx = i * 128 + tid;
            int r = idx >> 4, c = idx & 15;
            uint32_t off = fl_off(r, c);
            size_t g = krow0 + (size_t)r * DIM_ + c * 8;
            cp_async16(sKh + off, khi + g);
            cp_async16(sKl + off, klo + g);
            cp_async16(sVh + off, vhi + g);
            cp_async16(sVl + off, vlo + g);
        }
        CP_COMMIT();
        CP_WAIT(0);
        __syncthreads();

        // ---- S = Q @ K^T (bf16x3) ----
        float sacc[8][4];
#pragma unroll
        for (int nt = 0; nt < 8; nt++)
#pragma unroll
            for (int e = 0; e < 4; e++) sacc[nt][e] = 0.f;

#pragma unroll
        for (int kk = 0; kk < 8; kk++) {
            uint32_t aq[4], aql[4], bk[8][2];
            int arow = mbase + a_r;
            int achk = 2 * kk + a_cb;
            ldmatrix_x4(aq[0], aq[1], aq[2], aq[3], sQh + fl_off(arow, achk));
            ldmatrix_x4(aql[0], aql[1], aql[2], aql[3], sQl + fl_off(arow, achk));
#pragma unroll
            for (int np = 0; np < 4; np++) {
                int brow = (2 * np + bk_np) * 8 + bk_r;
                int bchk = 2 * kk + bk_cb;
                ldmatrix_x4(bk[2 * np][0], bk[2 * np][1],
                            bk[2 * np + 1][0], bk[2 * np + 1][1],
                            sKh + fl_off(brow, bchk));
            }
#pragma unroll
            for (int nt = 0; nt < 8; nt++) mma_bf16(sacc[nt], aq,  bk[nt]);
#pragma unroll
            for (int nt = 0; nt < 8; nt++) mma_bf16(sacc[nt], aql, bk[nt]);
#pragma unroll
            for (int np = 0; np < 4; np++) {
                int brow = (2 * np + bk_np) * 8 + bk_r;
                int bchk = 2 * kk + bk_cb;
                ldmatrix_x4(bk[2 * np][0], bk[2 * np][1],
                            bk[2 * np + 1][0], bk[2 * np + 1][1],
                            sKl + fl_off(brow, bchk));
            }
#pragma unroll
            for (int nt = 0; nt < 8; nt++) mma_bf16(sacc[nt], aq, bk[nt]);
        }

        // ---- causal mask (diagonal tile only) ----
        if (kb == qb) {
            int rowA = mbase + rA, rowB = rowA + 8;
#pragma unroll
            for (int nt = 0; nt < 8; nt++) {
                int c0 = nt * 8 + cq;
                if (c0     > rowA) sacc[nt][0] = -1e30f;
                if (c0 + 1 > rowA) sacc[nt][1] = -1e30f;
                if (c0     > rowB) sacc[nt][2] = -1e30f;
                if (c0 + 1 > rowB) sacc[nt][3] = -1e30f;
            }
        }

        // ---- online softmax (two rows per thread) ----
        float tmA = -1e30f, tmB = -1e30f;
#pragma unroll
        for (int nt = 0; nt < 8; nt++) {
            tmA = fmaxf(tmA, fmaxf(sacc[nt][0], sacc[nt][1]));
            tmB = fmaxf(tmB, fmaxf(sacc[nt][2], sacc[nt][3]));
        }
        tmA = fmaxf(tmA, __shfl_xor_sync(0xffffffffu, tmA, 1));
        tmA = fmaxf(tmA, __shfl_xor_sync(0xffffffffu, tmA, 2));
        tmB = fmaxf(tmB, __shfl_xor_sync(0xffffffffu, tmB, 1));
        tmB = fmaxf(tmB, __shfl_xor_sync(0xffffffffu, tmB, 2));

        float mn0 = fmaxf(m0, tmA), mn1 = fmaxf(m1, tmB);
        float alpha0 = fexp2((m0 - mn0) * KARG);
        float alpha1 = fexp2((m1 - mn1) * KARG);
        m0 = mn0; m1 = mn1;

        float rs0 = 0.f, rs1 = 0.f;
#pragma unroll
        for (int nt = 0; nt < 8; nt++) {
            float p0 = fexp2((sacc[nt][0] - m0) * KARG);
            float p1 = fexp2((sacc[nt][1] - m0) * KARG);
            float p2 = fexp2((sacc[nt][2] - m1) * KARG);
            float p3 = fexp2((sacc[nt][3] - m1) * KARG);
            sacc[nt][0] = p0; sacc[nt][1] = p1; sacc[nt][2] = p2; sacc[nt][3] = p3;
            rs0 += p0 + p1; rs1 += p2 + p3;
        }
        rs0 += __shfl_xor_sync(0xffffffffu, rs0, 1);
        rs0 += __shfl_xor_sync(0xffffffffu, rs0, 2);
        rs1 += __shfl_xor_sync(0xffffffffu, rs1, 1);
        rs1 += __shfl_xor_sync(0xffffffffu, rs1, 2);
        l0 = alpha0 * l0 + rs0;
        l1 = alpha1 * l1 + rs1;

#pragma unroll
        for (int nt = 0; nt < 16; nt++) {
            o[nt][0] *= alpha0; o[nt][1] *= alpha0;
            o[nt][2] *= alpha1; o[nt][3] *= alpha1;
        }

        // ---- pack P fragments (hi/lo) ----
        uint32_t phi[4][4], plo[4][4];
#pragma unroll
        for (int kk2 = 0; kk2 < 4; kk2++) {
            split_pack(sacc[2 * kk2][0],     sacc[2 * kk2][1],     phi[kk2][0], plo[kk2][0]);
            split_pack(sacc[2 * kk2][2],     sacc[2 * kk2][3],     phi[kk2][1], plo[kk2][1]);
            split_pack(sacc[2 * kk2 + 1][0], sacc[2 * kk2 + 1][1], phi[kk2][2], plo[kk2][2]);
            split_pack(sacc[2 * kk2 + 1][2], sacc[2 * kk2 + 1][3], phi[kk2][3], plo[kk2][3]);
        }

        // ---- O += P @ V (bf16x3) ----
#pragma unroll
        for (int kk2 = 0; kk2 < 4; kk2++) {
#pragma unroll
            for (int np = 0; np < 8; np++) {
                uint32_t bv[4];
                int vrow = kk2 * 16 + a_r;
                int vchk = 2 * np + a_cb;
                ldmatrix_x4_trans(bv[0], bv[1], bv[2], bv[3], sVh + fl_off(vrow, vchk));
                mma_bf16(o[2 * np],     phi[kk2], bv + 0);
                mma_bf16(o[2 * np + 1], phi[kk2], bv + 2);
                mma_bf16(o[2 * np],     plo[kk2], bv + 0);
                mma_bf16(o[2 * np + 1], plo[kk2], bv + 2);
                ldmatrix_x4_trans(bv[0], bv[1], bv[2], bv[3], sVl + fl_off(vrow, vchk));
                mma_bf16(o[2 * np],     phi[kk2], bv + 0);
                mma_bf16(o[2 * np + 1], phi[kk2], bv + 2);
            }
        }
    }

    // ---- epilogue: Ot[b, colbase+col, s] = o / l, split to bf16 hi/lo ----
    const float inv0 = 1.f / l0, inv1 = 1.f / l1;
    const int s0 = qbase + mbase + rA;
    const int s1 = s0 + 8;
#pragma unroll
    for (int nt = 0; nt < 16; nt++) {
        int col = colbase + nt * 8 + cq;
        size_t i00 = ((size_t)b * DIM_ + col) * S_;
        size_t i01 = i00 + S_;   // col+1
        float v00 = o[nt][0] * inv0, v01 = o[nt][1] * inv0;
        float v10 = o[nt][2] * inv1, v11 = o[nt][3] * inv1;
        __nv_bfloat16 hh, ll;
        hh = __float2bfloat16(v00); ll = __float2bfloat16(v00 - __bfloat162float(hh));
        othi[i00 + s0] = hh; otlo[i00 + s0] = ll;
        hh = __float2bfloat16(v01); ll = __float2bfloat16(v01 - __bfloat162float(hh));
        othi[i01 + s0] = hh; otlo[i01 + s0] = ll;
        hh = __float2bfloat16(v10); ll = __float2bfloat16(v10 - __bfloat162float(hh));
        othi[i00 + s1] = hh; otlo[i00 + s1] = ll;
        hh = __float2bfloat16(v11); ll = __float2bfloat16(v11 - __bfloat162float(hh));
        othi[i01 + s1] = hh; otlo[i01 + s1] = ll;
    }
}

// ---------------------------------------------------------------------------
// Launch
// ---------------------------------------------------------------------------
extern "C" void kernel_launch(void* const* d_in, const int* in_sizes, int n_in,
                              void* d_out, int out_size)
{
    const float* x    = (const float*)d_in[0];
    const float* Wq   = (const float*)d_in[1];
    const float* Wk   = (const float*)d_in[2];
    const float* Wv   = (const float*)d_in[3];
    const float* Wo   = (const float*)d_in[4];
    const float* cosb = (const float*)d_in[5];
    const float* sinb = (const float*)d_in[6];
    // d_in[7] = mask: causal handled analytically

    float *q, *k, *v;
    cudaGetSymbolAddress((void**)&q, g_q);
    cudaGetSymbolAddress((void**)&k, g_k);
    cudaGetSymbolAddress((void**)&v, g_v);

    __nv_bfloat16 *xhi, *xlo, *wqhi, *wqlo, *wkhi, *wklo, *wvhi, *wvlo, *wohi, *wolo;
    __nv_bfloat16 *qhi, *qlo, *khi, *klo, *vhi, *vlo, *othi, *otlo;
    cudaGetSymbolAddress((void**)&xhi,  g_xhi);
    cudaGetSymbolAddress((void**)&xlo,  g_xlo);
    cudaGetSymbolAddress((void**)&wqhi, g_wqhi);
    cudaGetSymbolAddress((void**)&wqlo, g_wqlo);
    cudaGetSymbolAddress((void**)&wkhi, g_wkhi);
    cudaGetSymbolAddress((void**)&wklo, g_wklo);
    cudaGetSymbolAddress((void**)&wvhi, g_wvhi);
    cudaGetSymbolAddress((void**)&wvlo, g_wvlo);
    cudaGetSymbolAddress((void**)&wohi, g_wohi);
    cudaGetSymbolAddress((void**)&wolo, g_wolo);
    cudaGetSymbolAddress((void**)&qhi,  g_qhi);
    cudaGetSymbolAddress((void**)&qlo,  g_qlo);
    cudaGetSymbolAddress((void**)&khi,  g_khi);
    cudaGetSymbolAddress((void**)&klo,  g_klo);
    cudaGetSymbolAddress((void**)&vhi,  g_vhi);
    cudaGetSymbolAddress((void**)&vlo,  g_vlo);
    cudaGetSymbolAddress((void**)&othi, g_othi);
    cudaGetSymbolAddress((void**)&otlo, g_otlo);

    cudaFuncSetAttribute(flash_mma, cudaFuncAttributeMaxDynamicSharedMemorySize, FL_SMEM);

    // Split inputs into bf16 hi/lo
    {
        int n4x = MROWS * DIM_ / 4;
        int n4w = DIM_ * DIM_ / 4;
        split_kernel<<<n4x / 256, 256>>>(x,  xhi,  xlo,  n4x);
        split_kernel<<<n4w / 256, 256>>>(Wq, wqhi, wqlo, n4w);
        split_kernel<<<n4w / 256, 256>>>(Wk, wkhi, wklo, n4w);
        split_kernel<<<n4w / 256, 256>>>(Wv, wvhi, wvlo, n4w);
        split_kernel<<<n4w / 256, 256>>>(Wo, wohi, wolo, n4w);
    }

    dim3 ggemm(DIM_ / GBN, MROWS / GBM);   // (16, 32)

    // QKV projections on tensor cores (bf16x3 split ~ fp32 accuracy)
    gemm_mma_bf16x3<<<ggemm, 256>>>(xhi, xlo, wqhi, wqlo, q, MROWS, DIM_, DIM_);
    gemm_mma_bf16x3<<<ggemm, 256>>>(xhi, xlo, wkhi, wklo, k, MROWS, DIM_, DIM_);
    gemm_mma_bf16x3<<<ggemm, 256>>>(xhi, xlo, wvhi, wvlo, v, MROWS, DIM_, DIM_);

    // RoPE + split q,k -> bf16 hi/lo ; split v
    int npairs = MROWS * (DIM_ / 2);
    rope_split<<<npairs / 256, 256>>>(q, k, cosb, sinb, qhi, qlo, khi, klo);
    split_kernel<<<(MROWS * DIM_ / 4) / 256, 256>>>(v, vhi, vlo, MROWS * DIM_ / 4);

    // Tensor-core causal flash attention -> othi/otlo transposed
    dim3 gflash(S_ / 64, H_, B_);          // (32, 16, 2)
    flash_mma<<<gflash, 128, FL_SMEM>>>(qhi, qlo, khi, klo, vhi, vlo, othi, otlo);

    // Output projection
    gemm_mma_bf16x3<<<ggemm, 256>>>(othi, otlo, wohi, wolo, (float*)d_out,
                                    MROWS, DIM_, DIM_);
}